// round 15
// baseline (speedup 1.0000x reference)
#include <cuda_runtime.h>
#include <cstdint>

#define B_SZ 512
#define I_SZ 256
#define H_SZ 512
#define ICH  8
#define NQ   4
#define NQS  2
#define NTILE 256   // (H/64) * (B/16)

// Transformed parameter planes (recurrent + sensory) and scratch
__device__ float g_SG[H_SZ*H_SZ];
__device__ float g_MS[H_SZ*H_SZ];
__device__ float g_WE[H_SZ*H_SZ];
__device__ float g_WW[H_SZ*H_SZ];
__device__ float s_SG[I_SZ*H_SZ];
__device__ float s_MS[I_SZ*H_SZ];
__device__ float s_WE[I_SZ*H_SZ];
__device__ float s_WW[I_SZ*H_SZ];
__device__ float g_CN[H_SZ];
__device__ float g_CD[H_SZ];
__device__ float g_A [B_SZ*H_SZ];
__device__ float g_Dc[B_SZ*H_SZ];
__device__ float g_v0[B_SZ*H_SZ];
__device__ float g_v1[B_SZ*H_SZ];
// Per-quarter partial sums (recurrent) and sensory partials (halves)
__device__ float g_Pn[NQ*B_SZ*H_SZ];
__device__ float g_Pd[NQ*B_SZ*H_SZ];
__device__ float g_PnS[NQS*B_SZ*H_SZ];
__device__ float g_PdS[NQS*B_SZ*H_SZ];
// Per-step, per-tile arrival counters (zeroed every replay in k_colsum)
__device__ unsigned g_cnt[6*NTILE];

__device__ __forceinline__ float tanh_fast(float x){
    float y;
    asm("tanh.approx.f32 %0, %1;" : "=f"(y) : "f"(x));
    return y;
}
__device__ __forceinline__ uint32_t saddr(const void* p){
    return (uint32_t)__cvta_generic_to_shared(p);
}
__device__ __forceinline__ void cp16(uint32_t dst, const void* src){
    asm volatile("cp.async.ca.shared.global [%0], [%1], 16;" :: "r"(dst), "l"(src));
}

// sigmoid((v-mu)*sigma) = 0.5*tanh(0.5*sigma*v - 0.5*sigma*mu) + 0.5
__global__ void k_prep(const float* __restrict__ mu, const float* __restrict__ sigma,
                       const float* __restrict__ W,  const float* __restrict__ erev,
                       const float* __restrict__ smu, const float* __restrict__ ssig,
                       const float* __restrict__ sW,  const float* __restrict__ serev){
    int idx = blockIdx.x*blockDim.x + threadIdx.x;
    if (idx < H_SZ*H_SZ){
        float s = sigma[idx], m = mu[idx], w = W[idx], e = erev[idx];
        g_SG[idx] = 0.5f*s;
        g_MS[idx] = -0.5f*s*m;
        g_WE[idx] = 0.5f*w*e;
        g_WW[idx] = 0.5f*w;
    } else if (idx < (H_SZ + I_SZ)*H_SZ){
        int j = idx - H_SZ*H_SZ;
        float s = ssig[j], m = smu[j], w = sW[j], e = serev[j];
        s_SG[j] = 0.5f*s;
        s_MS[j] = -0.5f*s*m;
        s_WE[j] = 0.5f*w*e;
        s_WW[j] = 0.5f*w;
    }
}

// Per-h constants from RAW inputs + counter reset (runs every replay).
__global__ void k_colsum(const float* __restrict__ W,  const float* __restrict__ erev,
                         const float* __restrict__ sW, const float* __restrict__ serev){
    int gid = blockIdx.x*blockDim.x + threadIdx.x;
    if (gid < 6*NTILE) g_cnt[gid] = 0u;

    int h0 = blockIdx.x * 32;
    int hh = threadIdx.x & 31;
    int it = threadIdx.x >> 5;
    float sn = 0.f, sd = 0.f;
    for (int i = it; i < H_SZ; i += 8){
        float w = W[i*H_SZ + h0 + hh], e = erev[i*H_SZ + h0 + hh];
        sn = fmaf(w, e, sn); sd += w;
    }
    for (int i = it; i < I_SZ; i += 8){
        float w = sW[i*H_SZ + h0 + hh], e = serev[i*H_SZ + h0 + hh];
        sn = fmaf(w, e, sn); sd += w;
    }
    __shared__ float rn[8][32], rd[8][32];
    rn[it][hh] = sn; rd[it][hh] = sd;
    __syncthreads();
    if (it == 0){
        float a = 0.f, b = 0.f;
        #pragma unroll
        for (int k = 0; k < 8; k++){ a += rn[k][hh]; b += rd[k][hh]; }
        g_CN[h0+hh] = 0.5f*a; g_CD[h0+hh] = 0.5f*b;
    }
}

// ---------------------------------------------------------------------------
// Partial core: one block = 64h x 16b tile x 128 i-rows. 128 threads = 4 warps;
// lane covers h = h0+2*lane+{0,1}; warp wq covers b = b0+4*wq+{0..3}.
// cp.async double buffer.
// ---------------------------------------------------------------------------
__device__ __forceinline__ void partial_core(
        const float* __restrict__ P0, const float* __restrict__ P1,
        const float* __restrict__ P2, const float* __restrict__ P3,
        const float* __restrict__ vin, int vstr, int h0, int b0, int ibase, int tx,
        float (&num)[4][2], float (&den)[4][2],
        float (*sp)[4][ICH][64], float (*vs)[16][ICH])
{
    const int lane = tx & 31;
    const int wq   = tx >> 5;
    const int NC   = 128 / ICH;

    const int prow = tx >> 4;
    const int pcol = (tx & 15) * 4;
    const int vrow = tx >> 1;
    const int vcol = (tx & 1) * 4;

    auto issue = [&](int c, int buf){
        int i0 = ibase + c * ICH;
        const float* bases[4] = {P0, P1, P2, P3};
        #pragma unroll
        for (int pl = 0; pl < 4; pl++)
            cp16(saddr(&sp[buf][pl][prow][pcol]), bases[pl] + (i0 + prow)*H_SZ + h0 + pcol);
        if (tx < 32)
            cp16(saddr(&vs[buf][vrow][vcol]), &vin[(b0 + vrow)*vstr + i0 + vcol]);
        asm volatile("cp.async.commit_group;");
    };

    int buf = 0;
    issue(0, 0);
    asm volatile("cp.async.wait_group 0;");
    __syncthreads();

    for (int c = 0; c < NC; c++){
        if (c + 1 < NC) issue(c + 1, buf ^ 1);
        #pragma unroll
        for (int ic = 0; ic < ICH; ic++){
            float2 SG = *(const float2*)&sp[buf][0][ic][2*lane];
            float2 MS = *(const float2*)&sp[buf][1][ic][2*lane];
            float2 WE = *(const float2*)&sp[buf][2][ic][2*lane];
            float2 WW = *(const float2*)&sp[buf][3][ic][2*lane];
            #pragma unroll
            for (int j = 0; j < 4; j++){
                float v = vs[buf][4*wq + j][ic];
                float t0 = tanh_fast(fmaf(v, SG.x, MS.x));
                float t1 = tanh_fast(fmaf(v, SG.y, MS.y));
                num[j][0] = fmaf(WE.x, t0, num[j][0]);
                den[j][0] = fmaf(WW.x, t0, den[j][0]);
                num[j][1] = fmaf(WE.y, t1, num[j][1]);
                den[j][1] = fmaf(WW.y, t1, den[j][1]);
            }
        }
        if (c + 1 < NC){
            asm volatile("cp.async.wait_group 0;");
            __syncthreads();
            buf ^= 1;
        }
    }
}

__device__ __forceinline__ void store_partials(float* Pn, float* Pd,
                                               int h0, int b0, int qt, int tx,
                                               float (&num)[4][2], float (&den)[4][2]){
    const int lane = tx & 31;
    const int wq   = tx >> 5;
    #pragma unroll
    for (int j = 0; j < 4; j++){
        int b = b0 + 4*wq + j;
        int ix = (qt*B_SZ + b)*H_SZ + h0 + 2*lane;
        *(float2*)&Pn[ix] = make_float2(num[j][0], num[j][1]);
        *(float2*)&Pd[ix] = make_float2(den[j][0], den[j][1]);
    }
}

// ---------------------------------------------------------------------------
// Fused partial + last-block combine. grid = (8, 32, NQ [+NQS when first]).
// After storing partials, each block arrives on the tile counter; the last
// arrival combines the tile (and on step 1 also builds A/Dc from sensory
// partials + per-h constants).
// ---------------------------------------------------------------------------
__global__ __launch_bounds__(128, 8) void k_step_fused(
        const float* vext, float* voutext, int sel_in, int sel_out, int first,
        const float* __restrict__ inp, const float* __restrict__ cm,
        const float* __restrict__ gleak, const float* __restrict__ vleak,
        int stepidx){
    __shared__ __align__(16) float sp[2][4][ICH][64];
    __shared__ __align__(16) float vs[2][16][ICH];
    __shared__ int s_last;

    const float* vin = (sel_in == 0) ? g_v0 : ((sel_in == 1) ? g_v1 : vext);
    const int h0 = blockIdx.x * 64, b0 = blockIdx.y * 16, qt = blockIdx.z;
    const int tx = threadIdx.x;
    float num[4][2] = {}, den[4][2] = {};

    if (first && qt >= NQ){
        int qs = qt - NQ;
        partial_core(s_SG, s_MS, s_WE, s_WW, inp, I_SZ,
                     h0, b0, qs*128, tx, num, den, sp, vs);
        store_partials(g_PnS, g_PdS, h0, b0, qs, tx, num, den);
    } else {
        partial_core(g_SG, g_MS, g_WE, g_WW, vin, H_SZ,
                     h0, b0, qt*128, tx, num, den, sp, vs);
        store_partials(g_Pn, g_Pd, h0, b0, qt, tx, num, den);
    }

    __threadfence();
    if (tx == 0){
        int tile = blockIdx.y * gridDim.x + blockIdx.x;
        unsigned tgt = first ? (NQ + NQS) : NQ;
        s_last = (atomicAdd(&g_cnt[stepidx*NTILE + tile], 1u) == tgt - 1u);
    }
    __syncthreads();
    if (!s_last) return;

    // ---- last block: combine this 64h x 16b tile ----
    __threadfence();
    float* vout = (sel_out == 0) ? g_v0 : ((sel_out == 1) ? g_v1 : voutext);
    const int b  = b0 + (tx >> 3);
    const int hb = h0 + (tx & 7) * 8;

    #pragma unroll
    for (int g = 0; g < 2; g++){
        int h = hb + g*4;
        int e = b*H_SZ + h;
        float4 a4, d4;
        if (first){
            float4 gl = *(const float4*)&gleak[h];
            float4 vl = *(const float4*)&vleak[h];
            float4 c4 = *(const float4*)&cm[h];
            float4 cn = *(const float4*)&g_CN[h];
            float4 cd = *(const float4*)&g_CD[h];
            a4.x = fmaf(gl.x, vl.x, cn.x); a4.y = fmaf(gl.y, vl.y, cn.y);
            a4.z = fmaf(gl.z, vl.z, cn.z); a4.w = fmaf(gl.w, vl.w, cn.w);
            d4.x = c4.x + gl.x + cd.x; d4.y = c4.y + gl.y + cd.y;
            d4.z = c4.z + gl.z + cd.z; d4.w = c4.w + gl.w + cd.w;
            #pragma unroll
            for (int q = 0; q < NQS; q++){
                float4 pn = *(const float4*)&g_PnS[q*B_SZ*H_SZ + e];
                float4 pd = *(const float4*)&g_PdS[q*B_SZ*H_SZ + e];
                a4.x += pn.x; a4.y += pn.y; a4.z += pn.z; a4.w += pn.w;
                d4.x += pd.x; d4.y += pd.y; d4.z += pd.z; d4.w += pd.w;
            }
            *(float4*)&g_A[e]  = a4;
            *(float4*)&g_Dc[e] = d4;
        } else {
            a4 = *(const float4*)&g_A[e];
            d4 = *(const float4*)&g_Dc[e];
        }

        float4 v4 = *(const float4*)&vin[e];
        float4 c4 = *(const float4*)&cm[h];
        float4 n;
        n.x = fmaf(c4.x, v4.x, a4.x); n.y = fmaf(c4.y, v4.y, a4.y);
        n.z = fmaf(c4.z, v4.z, a4.z); n.w = fmaf(c4.w, v4.w, a4.w);
        #pragma unroll
        for (int q = 0; q < NQ; q++){
            float4 pn = *(const float4*)&g_Pn[q*B_SZ*H_SZ + e];
            float4 pd = *(const float4*)&g_Pd[q*B_SZ*H_SZ + e];
            n.x += pn.x; n.y += pn.y; n.z += pn.z; n.w += pn.w;
            d4.x += pd.x; d4.y += pd.y; d4.z += pd.z; d4.w += pd.w;
        }
        float4 o;
        o.x = __fdividef(n.x, d4.x + 1e-8f);
        o.y = __fdividef(n.y, d4.y + 1e-8f);
        o.z = __fdividef(n.z, d4.z + 1e-8f);
        o.w = __fdividef(n.w, d4.w + 1e-8f);
        *(float4*)&vout[e] = o;
    }
}

extern "C" void kernel_launch(void* const* d_in, const int* in_sizes, int n_in,
                              void* d_out, int out_size){
    const float* inputs = (const float*)d_in[0];
    const float* state  = (const float*)d_in[1];
    const float* smu    = (const float*)d_in[2];
    const float* ssig   = (const float*)d_in[3];
    const float* sW     = (const float*)d_in[4];
    const float* serev  = (const float*)d_in[5];
    const float* mu     = (const float*)d_in[6];
    const float* sigma  = (const float*)d_in[7];
    const float* W      = (const float*)d_in[8];
    const float* erev   = (const float*)d_in[9];
    const float* vleak  = (const float*)d_in[10];
    const float* gleak  = (const float*)d_in[11];
    const float* cm     = (const float*)d_in[12];
    float* out = (float*)d_out;

    k_prep<<<((H_SZ+I_SZ)*H_SZ + 255)/256, 256>>>(mu, sigma, W, erev,
                                                  smu, ssig, sW, serev);
    k_colsum<<<H_SZ/32, 256>>>(W, erev, sW, serev);

    dim3 pgrid6(H_SZ/64, B_SZ/16, NQ + NQS);    // step 1 (+ sensory halves)
    dim3 pgrid4(H_SZ/64, B_SZ/16, NQ);

    // 6 unfolds: state -> v0 -> v1 -> v0 -> v1 -> v0 -> out
    const int seq_in [6] = {2, 0, 1, 0, 1, 0};
    const int seq_out[6] = {0, 1, 0, 1, 0, 2};
    for (int s = 0; s < 6; s++){
        const float* vext = (seq_in[s]  == 2) ? state : nullptr;
        float*       oext = (seq_out[s] == 2) ? out   : nullptr;
        if (s == 0)
            k_step_fused<<<pgrid6, 128>>>(vext, oext, seq_in[s], seq_out[s], 1,
                                          inputs, cm, gleak, vleak, s);
        else
            k_step_fused<<<pgrid4, 128>>>(vext, oext, seq_in[s], seq_out[s], 0,
                                          nullptr, cm, gleak, vleak, s);
    }
}

// round 16
// speedup vs baseline: 1.0004x; 1.0004x over previous
#include <cuda_runtime.h>
#include <cstdint>

#define B_SZ 512
#define I_SZ 256
#define H_SZ 512
#define ICH  8
#define NQ   4
#define NQS  2

// Transformed parameter planes (recurrent + sensory) and scratch
__device__ float g_SG[H_SZ*H_SZ];
__device__ float g_MS[H_SZ*H_SZ];
__device__ float g_WE[H_SZ*H_SZ];
__device__ float g_WW[H_SZ*H_SZ];
__device__ float s_SG[I_SZ*H_SZ];
__device__ float s_MS[I_SZ*H_SZ];
__device__ float s_WE[I_SZ*H_SZ];
__device__ float s_WW[I_SZ*H_SZ];
__device__ float g_CN[H_SZ];
__device__ float g_CD[H_SZ];
__device__ float g_A [B_SZ*H_SZ];
__device__ float g_Dc[B_SZ*H_SZ];
__device__ float g_v0[B_SZ*H_SZ];
__device__ float g_v1[B_SZ*H_SZ];
// Per-quarter partial sums (recurrent steps) and sensory partials (halves)
__device__ float g_Pn[NQ*B_SZ*H_SZ];
__device__ float g_Pd[NQ*B_SZ*H_SZ];
__device__ float g_PnS[NQS*B_SZ*H_SZ];
__device__ float g_PdS[NQS*B_SZ*H_SZ];

__device__ __forceinline__ float tanh_fast(float x){
    float y;
    asm("tanh.approx.f32 %0, %1;" : "=f"(y) : "f"(x));
    return y;
}
// 2 tanh in one MUFU op via f16x2 (quantization ~5e-4 per element).
__device__ __forceinline__ void tanh2_fast(float a0, float a1, float& t0, float& t1){
    uint32_t p, t;
    asm("cvt.rn.f16x2.f32 %0, %1, %2;" : "=r"(p) : "f"(a1), "f"(a0));  // hi=a1, lo=a0
    asm("tanh.approx.f16x2 %0, %1;" : "=r"(t) : "r"(p));
    asm("{ .reg .b16 lo, hi;\n\t"
        "  mov.b32 {lo, hi}, %2;\n\t"
        "  cvt.f32.f16 %0, lo;\n\t"
        "  cvt.f32.f16 %1, hi; }"
        : "=f"(t0), "=f"(t1) : "r"(t));
}
__device__ __forceinline__ uint32_t saddr(const void* p){
    return (uint32_t)__cvta_generic_to_shared(p);
}
__device__ __forceinline__ void cp16(uint32_t dst, const void* src){
    asm volatile("cp.async.ca.shared.global [%0], [%1], 16;" :: "r"(dst), "l"(src));
}

// sigmoid((v-mu)*sigma) = 0.5*tanh(0.5*sigma*v - 0.5*sigma*mu) + 0.5
__global__ void k_prep(const float* __restrict__ mu, const float* __restrict__ sigma,
                       const float* __restrict__ W,  const float* __restrict__ erev,
                       const float* __restrict__ smu, const float* __restrict__ ssig,
                       const float* __restrict__ sW,  const float* __restrict__ serev){
    int idx = blockIdx.x*blockDim.x + threadIdx.x;
    if (idx < H_SZ*H_SZ){
        float s = sigma[idx], m = mu[idx], w = W[idx], e = erev[idx];
        g_SG[idx] = 0.5f*s;
        g_MS[idx] = -0.5f*s*m;
        g_WE[idx] = 0.5f*w*e;
        g_WW[idx] = 0.5f*w;
    } else if (idx < (H_SZ + I_SZ)*H_SZ){
        int j = idx - H_SZ*H_SZ;
        float s = ssig[j], m = smu[j], w = sW[j], e = serev[j];
        s_SG[j] = 0.5f*s;
        s_MS[j] = -0.5f*s*m;
        s_WE[j] = 0.5f*w*e;
        s_WW[j] = 0.5f*w;
    }
}

// Per-h constants from RAW inputs:
// CN[h] = 0.5*( sum_i W*erev (recur) + sum_i sW*serev (sens) ), CD likewise.
__global__ void k_colsum(const float* __restrict__ W,  const float* __restrict__ erev,
                         const float* __restrict__ sW, const float* __restrict__ serev){
    int h0 = blockIdx.x * 32;
    int hh = threadIdx.x & 31;
    int it = threadIdx.x >> 5;
    float sn = 0.f, sd = 0.f;
    for (int i = it; i < H_SZ; i += 8){
        float w = W[i*H_SZ + h0 + hh], e = erev[i*H_SZ + h0 + hh];
        sn = fmaf(w, e, sn); sd += w;
    }
    for (int i = it; i < I_SZ; i += 8){
        float w = sW[i*H_SZ + h0 + hh], e = serev[i*H_SZ + h0 + hh];
        sn = fmaf(w, e, sn); sd += w;
    }
    __shared__ float rn[8][32], rd[8][32];
    rn[it][hh] = sn; rd[it][hh] = sd;
    __syncthreads();
    if (it == 0){
        float a = 0.f, b = 0.f;
        #pragma unroll
        for (int k = 0; k < 8; k++){ a += rn[k][hh]; b += rd[k][hh]; }
        g_CN[h0+hh] = 0.5f*a; g_CD[h0+hh] = 0.5f*b;
    }
}

// ---------------------------------------------------------------------------
// Partial core: one block = 64h x 16b tile x 128 i-rows. 128 threads = 4 warps;
// lane covers h = h0+2*lane+{0,1} (conflict-free LDS.64 params); warp wq covers
// b = b0+4*wq+{0..3} (broadcast v). cp.async double buffer.
// tanh: even chunks use f16x2 MUFU (2 elem/op), odd chunks f32 — every output
// mixes both, keeping error ~0.5x of all-f16 while cutting MUFU cycles 25%.
// ---------------------------------------------------------------------------
__device__ __forceinline__ void partial_core(
        const float* __restrict__ P0, const float* __restrict__ P1,
        const float* __restrict__ P2, const float* __restrict__ P3,
        const float* __restrict__ vin, int vstr, int h0, int b0, int ibase, int tx,
        float (&num)[4][2], float (&den)[4][2],
        float (*sp)[4][ICH][64], float (*vs)[16][ICH])
{
    const int lane = tx & 31;
    const int wq   = tx >> 5;
    const int NC   = 128 / ICH;        // 16 chunks

    const int prow = tx >> 4;          // 0..7
    const int pcol = (tx & 15) * 4;    // 0..60
    const int vrow = tx >> 1;          // 0..15 (batch)
    const int vcol = (tx & 1) * 4;     // 0 or 4 (i)

    auto issue = [&](int c, int buf){
        int i0 = ibase + c * ICH;
        const float* bases[4] = {P0, P1, P2, P3};
        #pragma unroll
        for (int pl = 0; pl < 4; pl++)
            cp16(saddr(&sp[buf][pl][prow][pcol]), bases[pl] + (i0 + prow)*H_SZ + h0 + pcol);
        if (tx < 32)
            cp16(saddr(&vs[buf][vrow][vcol]), &vin[(b0 + vrow)*vstr + i0 + vcol]);
        asm volatile("cp.async.commit_group;");
    };

    int buf = 0;
    issue(0, 0);
    asm volatile("cp.async.wait_group 0;");
    __syncthreads();

    for (int c = 0; c < NC; c++){
        if (c + 1 < NC) issue(c + 1, buf ^ 1);
        if ((c & 1) == 0){
            // f16x2 tanh chunks
            #pragma unroll
            for (int ic = 0; ic < ICH; ic++){
                float2 SG = *(const float2*)&sp[buf][0][ic][2*lane];
                float2 MS = *(const float2*)&sp[buf][1][ic][2*lane];
                float2 WE = *(const float2*)&sp[buf][2][ic][2*lane];
                float2 WW = *(const float2*)&sp[buf][3][ic][2*lane];
                #pragma unroll
                for (int j = 0; j < 4; j++){
                    float v = vs[buf][4*wq + j][ic];
                    float a0 = fmaf(v, SG.x, MS.x);
                    float a1 = fmaf(v, SG.y, MS.y);
                    float t0, t1;
                    tanh2_fast(a0, a1, t0, t1);
                    num[j][0] = fmaf(WE.x, t0, num[j][0]);
                    den[j][0] = fmaf(WW.x, t0, den[j][0]);
                    num[j][1] = fmaf(WE.y, t1, num[j][1]);
                    den[j][1] = fmaf(WW.y, t1, den[j][1]);
                }
            }
        } else {
            // f32 tanh chunks
            #pragma unroll
            for (int ic = 0; ic < ICH; ic++){
                float2 SG = *(const float2*)&sp[buf][0][ic][2*lane];
                float2 MS = *(const float2*)&sp[buf][1][ic][2*lane];
                float2 WE = *(const float2*)&sp[buf][2][ic][2*lane];
                float2 WW = *(const float2*)&sp[buf][3][ic][2*lane];
                #pragma unroll
                for (int j = 0; j < 4; j++){
                    float v = vs[buf][4*wq + j][ic];
                    float t0 = tanh_fast(fmaf(v, SG.x, MS.x));
                    float t1 = tanh_fast(fmaf(v, SG.y, MS.y));
                    num[j][0] = fmaf(WE.x, t0, num[j][0]);
                    den[j][0] = fmaf(WW.x, t0, den[j][0]);
                    num[j][1] = fmaf(WE.y, t1, num[j][1]);
                    den[j][1] = fmaf(WW.y, t1, den[j][1]);
                }
            }
        }
        if (c + 1 < NC){
            asm volatile("cp.async.wait_group 0;");
            __syncthreads();
            buf ^= 1;
        }
    }
}

__device__ __forceinline__ void store_partials(float* Pn, float* Pd,
                                               int h0, int b0, int qt, int tx,
                                               float (&num)[4][2], float (&den)[4][2]){
    const int lane = tx & 31;
    const int wq   = tx >> 5;
    #pragma unroll
    for (int j = 0; j < 4; j++){
        int b = b0 + 4*wq + j;
        int ix = (qt*B_SZ + b)*H_SZ + h0 + 2*lane;
        *(float2*)&Pn[ix] = make_float2(num[j][0], num[j][1]);
        *(float2*)&Pd[ix] = make_float2(den[j][0], den[j][1]);
    }
}

// Recurrent partial; when with_sens, grid.z = 6 and z in [4,6) computes the
// sensory halves (inputs, I-planes) into g_PnS/g_PdS.
__global__ __launch_bounds__(128, 8) void k_step_partial(
        const float* vext, int sel_in, const float* __restrict__ inp, int with_sens){
    __shared__ __align__(16) float sp[2][4][ICH][64];
    __shared__ __align__(16) float vs[2][16][ICH];
    const int h0 = blockIdx.x * 64, b0 = blockIdx.y * 16, qt = blockIdx.z;
    const int tx = threadIdx.x;
    float num[4][2] = {}, den[4][2] = {};

    if (with_sens && qt >= NQ){
        int qs = qt - NQ;                       // sensory half 0/1
        partial_core(s_SG, s_MS, s_WE, s_WW, inp, I_SZ,
                     h0, b0, qs*128, tx, num, den, sp, vs);
        store_partials(g_PnS, g_PdS, h0, b0, qs, tx, num, den);
    } else {
        const float* vin = (sel_in == 0) ? g_v0 : ((sel_in == 1) ? g_v1 : vext);
        partial_core(g_SG, g_MS, g_WE, g_WW, vin, H_SZ,
                     h0, b0, qt*128, tx, num, den, sp, vs);
        store_partials(g_Pn, g_Pd, h0, b0, qt, tx, num, den);
    }
}

// Step combine: 512 blocks x 256 threads, float2 per thread.
// first=1: also build A/Dc from sensory partials + constants.
__global__ __launch_bounds__(256) void k_step_combine(
        const float* vext, float* voutext, int sel_in, int sel_out, int first,
        const float* __restrict__ cm, const float* __restrict__ gleak,
        const float* __restrict__ vleak){
    const float* vin  = (sel_in  == 0) ? g_v0 : ((sel_in  == 1) ? g_v1 : vext);
    float*       vout = (sel_out == 0) ? g_v0 : ((sel_out == 1) ? g_v1 : voutext);
    int e = (blockIdx.x*256 + threadIdx.x) * 2;
    int h = e & (H_SZ - 1);

    float2 a2, d2;
    if (first){
        float2 gl = *(const float2*)&gleak[h];
        float2 vl = *(const float2*)&vleak[h];
        float2 c2 = *(const float2*)&cm[h];
        float2 cn = *(const float2*)&g_CN[h];
        float2 cd = *(const float2*)&g_CD[h];
        a2.x = fmaf(gl.x, vl.x, cn.x); a2.y = fmaf(gl.y, vl.y, cn.y);
        d2.x = c2.x + gl.x + cd.x;     d2.y = c2.y + gl.y + cd.y;
        #pragma unroll
        for (int q = 0; q < NQS; q++){
            float2 pn = __ldg((const float2*)&g_PnS[q*B_SZ*H_SZ + e]);
            float2 pd = __ldg((const float2*)&g_PdS[q*B_SZ*H_SZ + e]);
            a2.x += pn.x; a2.y += pn.y;
            d2.x += pd.x; d2.y += pd.y;
        }
        *(float2*)&g_A[e]  = a2;
        *(float2*)&g_Dc[e] = d2;
    } else {
        a2 = *(const float2*)&g_A[e];
        d2 = *(const float2*)&g_Dc[e];
    }

    float2 v2 = *(const float2*)&vin[e];
    float2 c2 = *(const float2*)&cm[h];
    float2 n;
    n.x = fmaf(c2.x, v2.x, a2.x); n.y = fmaf(c2.y, v2.y, a2.y);
    #pragma unroll
    for (int q = 0; q < NQ; q++){
        float2 pn = __ldg((const float2*)&g_Pn[q*B_SZ*H_SZ + e]);
        float2 pd = __ldg((const float2*)&g_Pd[q*B_SZ*H_SZ + e]);
        n.x += pn.x; n.y += pn.y;
        d2.x += pd.x; d2.y += pd.y;
    }
    float2 o;
    o.x = __fdividef(n.x, d2.x + 1e-8f);
    o.y = __fdividef(n.y, d2.y + 1e-8f);
    *(float2*)&vout[e] = o;
}

extern "C" void kernel_launch(void* const* d_in, const int* in_sizes, int n_in,
                              void* d_out, int out_size){
    const float* inputs = (const float*)d_in[0];
    const float* state  = (const float*)d_in[1];
    const float* smu    = (const float*)d_in[2];
    const float* ssig   = (const float*)d_in[3];
    const float* sW     = (const float*)d_in[4];
    const float* serev  = (const float*)d_in[5];
    const float* mu     = (const float*)d_in[6];
    const float* sigma  = (const float*)d_in[7];
    const float* W      = (const float*)d_in[8];
    const float* erev   = (const float*)d_in[9];
    const float* vleak  = (const float*)d_in[10];
    const float* gleak  = (const float*)d_in[11];
    const float* cm     = (const float*)d_in[12];
    float* out = (float*)d_out;

    k_prep<<<((H_SZ+I_SZ)*H_SZ + 255)/256, 256>>>(mu, sigma, W, erev,
                                                  smu, ssig, sW, serev);
    k_colsum<<<H_SZ/32, 256>>>(W, erev, sW, serev);

    dim3 pgrid6(H_SZ/64, B_SZ/16, NQ + NQS);    // (8, 32, 6): step1 + sensory
    dim3 pgrid4(H_SZ/64, B_SZ/16, NQ);          // (8, 32, 4)
    const int cgrid = B_SZ*H_SZ/(256*2);        // 512 blocks x 256 threads

    // 6 unfolds: state -> v0 -> v1 -> v0 -> v1 -> v0 -> out
    const int seq_in [6] = {2, 0, 1, 0, 1, 0};
    const int seq_out[6] = {0, 1, 0, 1, 0, 2};
    for (int s = 0; s < 6; s++){
        const float* vext = (seq_in[s]  == 2) ? state : nullptr;
        float*       oext = (seq_out[s] == 2) ? out   : nullptr;
        if (s == 0)
            k_step_partial<<<pgrid6, 128>>>(vext, seq_in[s], inputs, 1);
        else
            k_step_partial<<<pgrid4, 128>>>(vext, seq_in[s], nullptr, 0);
        k_step_combine<<<cgrid, 256>>>(vext, oext, seq_in[s], seq_out[s],
                                       s == 0 ? 1 : 0, cm, gleak, vleak);
    }
}

// round 17
// speedup vs baseline: 1.0166x; 1.0162x over previous
#include <cuda_runtime.h>
#include <cstdint>

#define B_SZ 512
#define I_SZ 256
#define H_SZ 512
#define ICH  8
#define NQ   4
#define NQS  2

// Transformed parameter planes (recurrent + sensory) and scratch
__device__ float g_SG[H_SZ*H_SZ];
__device__ float g_MS[H_SZ*H_SZ];
__device__ float g_WE[H_SZ*H_SZ];
__device__ float g_WW[H_SZ*H_SZ];
__device__ float s_SG[I_SZ*H_SZ];
__device__ float s_MS[I_SZ*H_SZ];
__device__ float s_WE[I_SZ*H_SZ];
__device__ float s_WW[I_SZ*H_SZ];
__device__ float g_CN[H_SZ];
__device__ float g_CD[H_SZ];
__device__ float g_A [B_SZ*H_SZ];
__device__ float g_Dc[B_SZ*H_SZ];
__device__ float g_v0[B_SZ*H_SZ];
__device__ float g_v1[B_SZ*H_SZ];
// Per-quarter partial sums (recurrent steps) and sensory partials (halves)
__device__ float g_Pn[NQ*B_SZ*H_SZ];
__device__ float g_Pd[NQ*B_SZ*H_SZ];
__device__ float g_PnS[NQS*B_SZ*H_SZ];
__device__ float g_PdS[NQS*B_SZ*H_SZ];

__device__ __forceinline__ float tanh_fast(float x){
    float y;
    asm("tanh.approx.f32 %0, %1;" : "=f"(y) : "f"(x));
    return y;
}
__device__ __forceinline__ uint32_t saddr(const void* p){
    return (uint32_t)__cvta_generic_to_shared(p);
}
__device__ __forceinline__ void cp16(uint32_t dst, const void* src){
    asm volatile("cp.async.ca.shared.global [%0], [%1], 16;" :: "r"(dst), "l"(src));
}
// L2 cache policies
__device__ __forceinline__ uint64_t pol_evict_last(){
    uint64_t p;
    asm("createpolicy.fractional.L2::evict_last.b64 %0, 1.0;" : "=l"(p));
    return p;
}
__device__ __forceinline__ uint64_t pol_evict_first(){
    uint64_t p;
    asm("createpolicy.fractional.L2::evict_first.b64 %0, 1.0;" : "=l"(p));
    return p;
}
__device__ __forceinline__ void st2_hint(float* ptr, float x, float y, uint64_t pol){
    asm volatile("st.global.L2::cache_hint.v2.f32 [%0], {%1, %2}, %3;"
                 :: "l"(ptr), "f"(x), "f"(y), "l"(pol) : "memory");
}
__device__ __forceinline__ float2 ld2_hint(const float* ptr, uint64_t pol){
    float2 r;
    asm volatile("ld.global.L2::cache_hint.v2.f32 {%0, %1}, [%2], %3;"
                 : "=f"(r.x), "=f"(r.y) : "l"(ptr), "l"(pol));
    return r;
}

// sigmoid((v-mu)*sigma) = 0.5*tanh(0.5*sigma*v - 0.5*sigma*mu) + 0.5
__global__ void k_prep(const float* __restrict__ mu, const float* __restrict__ sigma,
                       const float* __restrict__ W,  const float* __restrict__ erev,
                       const float* __restrict__ smu, const float* __restrict__ ssig,
                       const float* __restrict__ sW,  const float* __restrict__ serev){
    int idx = blockIdx.x*blockDim.x + threadIdx.x;
    if (idx < H_SZ*H_SZ){
        float s = sigma[idx], m = mu[idx], w = W[idx], e = erev[idx];
        g_SG[idx] = 0.5f*s;
        g_MS[idx] = -0.5f*s*m;
        g_WE[idx] = 0.5f*w*e;
        g_WW[idx] = 0.5f*w;
    } else if (idx < (H_SZ + I_SZ)*H_SZ){
        int j = idx - H_SZ*H_SZ;
        float s = ssig[j], m = smu[j], w = sW[j], e = serev[j];
        s_SG[j] = 0.5f*s;
        s_MS[j] = -0.5f*s*m;
        s_WE[j] = 0.5f*w*e;
        s_WW[j] = 0.5f*w;
    }
}

// Per-h constants from RAW inputs:
// CN[h] = 0.5*( sum_i W*erev (recur) + sum_i sW*serev (sens) ), CD likewise.
__global__ void k_colsum(const float* __restrict__ W,  const float* __restrict__ erev,
                         const float* __restrict__ sW, const float* __restrict__ serev){
    int h0 = blockIdx.x * 32;
    int hh = threadIdx.x & 31;
    int it = threadIdx.x >> 5;
    float sn = 0.f, sd = 0.f;
    for (int i = it; i < H_SZ; i += 8){
        float w = W[i*H_SZ + h0 + hh], e = erev[i*H_SZ + h0 + hh];
        sn = fmaf(w, e, sn); sd += w;
    }
    for (int i = it; i < I_SZ; i += 8){
        float w = sW[i*H_SZ + h0 + hh], e = serev[i*H_SZ + h0 + hh];
        sn = fmaf(w, e, sn); sd += w;
    }
    __shared__ float rn[8][32], rd[8][32];
    rn[it][hh] = sn; rd[it][hh] = sd;
    __syncthreads();
    if (it == 0){
        float a = 0.f, b = 0.f;
        #pragma unroll
        for (int k = 0; k < 8; k++){ a += rn[k][hh]; b += rd[k][hh]; }
        g_CN[h0+hh] = 0.5f*a; g_CD[h0+hh] = 0.5f*b;
    }
}

// ---------------------------------------------------------------------------
// Partial core: one block = 64h x 16b tile x 128 i-rows. 128 threads = 4 warps;
// lane covers h = h0+2*lane+{0,1} (conflict-free LDS.64 params); warp wq covers
// b = b0+4*wq+{0..3} (broadcast v). cp.async double buffer. f32 tanh.
// ---------------------------------------------------------------------------
__device__ __forceinline__ void partial_core(
        const float* __restrict__ P0, const float* __restrict__ P1,
        const float* __restrict__ P2, const float* __restrict__ P3,
        const float* __restrict__ vin, int vstr, int h0, int b0, int ibase, int tx,
        float (&num)[4][2], float (&den)[4][2],
        float (*sp)[4][ICH][64], float (*vs)[16][ICH])
{
    const int lane = tx & 31;
    const int wq   = tx >> 5;
    const int NC   = 128 / ICH;        // 16 chunks

    const int prow = tx >> 4;          // 0..7
    const int pcol = (tx & 15) * 4;    // 0..60
    const int vrow = tx >> 1;          // 0..15 (batch)
    const int vcol = (tx & 1) * 4;     // 0 or 4 (i)

    auto issue = [&](int c, int buf){
        int i0 = ibase + c * ICH;
        const float* bases[4] = {P0, P1, P2, P3};
        #pragma unroll
        for (int pl = 0; pl < 4; pl++)
            cp16(saddr(&sp[buf][pl][prow][pcol]), bases[pl] + (i0 + prow)*H_SZ + h0 + pcol);
        if (tx < 32)
            cp16(saddr(&vs[buf][vrow][vcol]), &vin[(b0 + vrow)*vstr + i0 + vcol]);
        asm volatile("cp.async.commit_group;");
    };

    int buf = 0;
    issue(0, 0);
    asm volatile("cp.async.wait_group 0;");
    __syncthreads();

    for (int c = 0; c < NC; c++){
        if (c + 1 < NC) issue(c + 1, buf ^ 1);
        #pragma unroll
        for (int ic = 0; ic < ICH; ic++){
            float2 SG = *(const float2*)&sp[buf][0][ic][2*lane];
            float2 MS = *(const float2*)&sp[buf][1][ic][2*lane];
            float2 WE = *(const float2*)&sp[buf][2][ic][2*lane];
            float2 WW = *(const float2*)&sp[buf][3][ic][2*lane];
            #pragma unroll
            for (int j = 0; j < 4; j++){
                float v = vs[buf][4*wq + j][ic];
                float t0 = tanh_fast(fmaf(v, SG.x, MS.x));
                float t1 = tanh_fast(fmaf(v, SG.y, MS.y));
                num[j][0] = fmaf(WE.x, t0, num[j][0]);
                den[j][0] = fmaf(WW.x, t0, den[j][0]);
                num[j][1] = fmaf(WE.y, t1, num[j][1]);
                den[j][1] = fmaf(WW.y, t1, den[j][1]);
            }
        }
        if (c + 1 < NC){
            asm volatile("cp.async.wait_group 0;");
            __syncthreads();
            buf ^= 1;
        }
    }
}

// Store partials with L2 evict_last (combine reads them next kernel).
__device__ __forceinline__ void store_partials(float* Pn, float* Pd,
                                               int h0, int b0, int qt, int tx,
                                               float (&num)[4][2], float (&den)[4][2]){
    const int lane = tx & 31;
    const int wq   = tx >> 5;
    uint64_t pol = pol_evict_last();
    #pragma unroll
    for (int j = 0; j < 4; j++){
        int b = b0 + 4*wq + j;
        int ix = (qt*B_SZ + b)*H_SZ + h0 + 2*lane;
        st2_hint(&Pn[ix], num[j][0], num[j][1], pol);
        st2_hint(&Pd[ix], den[j][0], den[j][1], pol);
    }
}

// Recurrent partial; when with_sens, grid.z = 6 and z in [4,6) computes the
// sensory halves (inputs, I-planes) into g_PnS/g_PdS.
__global__ __launch_bounds__(128, 8) void k_step_partial(
        const float* vext, int sel_in, const float* __restrict__ inp, int with_sens){
    __shared__ __align__(16) float sp[2][4][ICH][64];
    __shared__ __align__(16) float vs[2][16][ICH];
    const int h0 = blockIdx.x * 64, b0 = blockIdx.y * 16, qt = blockIdx.z;
    const int tx = threadIdx.x;
    float num[4][2] = {}, den[4][2] = {};

    if (with_sens && qt >= NQ){
        int qs = qt - NQ;                       // sensory half 0/1
        partial_core(s_SG, s_MS, s_WE, s_WW, inp, I_SZ,
                     h0, b0, qs*128, tx, num, den, sp, vs);
        store_partials(g_PnS, g_PdS, h0, b0, qs, tx, num, den);
    } else {
        const float* vin = (sel_in == 0) ? g_v0 : ((sel_in == 1) ? g_v1 : vext);
        partial_core(g_SG, g_MS, g_WE, g_WW, vin, H_SZ,
                     h0, b0, qt*128, tx, num, den, sp, vs);
        store_partials(g_Pn, g_Pd, h0, b0, qt, tx, num, den);
    }
}

// Step combine: 512 blocks x 256 threads, float2 per thread.
// Partials read with evict_first (dead after); vout stored evict_last
// (next partial re-reads it). first=1: also build A/Dc.
__global__ __launch_bounds__(256) void k_step_combine(
        const float* vext, float* voutext, int sel_in, int sel_out, int first,
        const float* __restrict__ cm, const float* __restrict__ gleak,
        const float* __restrict__ vleak){
    const float* vin  = (sel_in  == 0) ? g_v0 : ((sel_in  == 1) ? g_v1 : vext);
    float*       vout = (sel_out == 0) ? g_v0 : ((sel_out == 1) ? g_v1 : voutext);
    int e = (blockIdx.x*256 + threadIdx.x) * 2;
    int h = e & (H_SZ - 1);
    uint64_t pf = pol_evict_first();
    uint64_t pl = pol_evict_last();

    float2 a2, d2;
    if (first){
        float2 gl = *(const float2*)&gleak[h];
        float2 vl = *(const float2*)&vleak[h];
        float2 c2 = *(const float2*)&cm[h];
        float2 cn = *(const float2*)&g_CN[h];
        float2 cd = *(const float2*)&g_CD[h];
        a2.x = fmaf(gl.x, vl.x, cn.x); a2.y = fmaf(gl.y, vl.y, cn.y);
        d2.x = c2.x + gl.x + cd.x;     d2.y = c2.y + gl.y + cd.y;
        #pragma unroll
        for (int q = 0; q < NQS; q++){
            float2 pn = ld2_hint(&g_PnS[q*B_SZ*H_SZ + e], pf);
            float2 pd = ld2_hint(&g_PdS[q*B_SZ*H_SZ + e], pf);
            a2.x += pn.x; a2.y += pn.y;
            d2.x += pd.x; d2.y += pd.y;
        }
        st2_hint(&g_A[e],  a2.x, a2.y, pl);
        st2_hint(&g_Dc[e], d2.x, d2.y, pl);
    } else {
        a2 = *(const float2*)&g_A[e];
        d2 = *(const float2*)&g_Dc[e];
    }

    float2 v2 = *(const float2*)&vin[e];
    float2 c2 = *(const float2*)&cm[h];
    float2 n;
    n.x = fmaf(c2.x, v2.x, a2.x); n.y = fmaf(c2.y, v2.y, a2.y);
    #pragma unroll
    for (int q = 0; q < NQ; q++){
        float2 pn = ld2_hint(&g_Pn[q*B_SZ*H_SZ + e], pf);
        float2 pd = ld2_hint(&g_Pd[q*B_SZ*H_SZ + e], pf);
        n.x += pn.x; n.y += pn.y;
        d2.x += pd.x; d2.y += pd.y;
    }
    float ox = __fdividef(n.x, d2.x + 1e-8f);
    float oy = __fdividef(n.y, d2.y + 1e-8f);
    st2_hint(&vout[e], ox, oy, pl);
}

extern "C" void kernel_launch(void* const* d_in, const int* in_sizes, int n_in,
                              void* d_out, int out_size){
    const float* inputs = (const float*)d_in[0];
    const float* state  = (const float*)d_in[1];
    const float* smu    = (const float*)d_in[2];
    const float* ssig   = (const float*)d_in[3];
    const float* sW     = (const float*)d_in[4];
    const float* serev  = (const float*)d_in[5];
    const float* mu     = (const float*)d_in[6];
    const float* sigma  = (const float*)d_in[7];
    const float* W      = (const float*)d_in[8];
    const float* erev   = (const float*)d_in[9];
    const float* vleak  = (const float*)d_in[10];
    const float* gleak  = (const float*)d_in[11];
    const float* cm     = (const float*)d_in[12];
    float* out = (float*)d_out;

    k_prep<<<((H_SZ+I_SZ)*H_SZ + 255)/256, 256>>>(mu, sigma, W, erev,
                                                  smu, ssig, sW, serev);
    k_colsum<<<H_SZ/32, 256>>>(W, erev, sW, serev);

    dim3 pgrid6(H_SZ/64, B_SZ/16, NQ + NQS);    // (8, 32, 6): step1 + sensory
    dim3 pgrid4(H_SZ/64, B_SZ/16, NQ);          // (8, 32, 4)
    const int cgrid = B_SZ*H_SZ/(256*2);        // 512 blocks x 256 threads

    // 6 unfolds: state -> v0 -> v1 -> v0 -> v1 -> v0 -> out
    const int seq_in [6] = {2, 0, 1, 0, 1, 0};
    const int seq_out[6] = {0, 1, 0, 1, 0, 2};
    for (int s = 0; s < 6; s++){
        const float* vext = (seq_in[s]  == 2) ? state : nullptr;
        float*       oext = (seq_out[s] == 2) ? out   : nullptr;
        if (s == 0)
            k_step_partial<<<pgrid6, 128>>>(vext, seq_in[s], inputs, 1);
        else
            k_step_partial<<<pgrid4, 128>>>(vext, seq_in[s], nullptr, 0);
        k_step_combine<<<cgrid, 256>>>(vext, oext, seq_in[s], seq_out[s],
                                       s == 0 ? 1 : 0, cm, gleak, vleak);
    }
}